// round 1
// baseline (speedup 1.0000x reference)
#include <cuda_runtime.h>
#include <math.h>

#define BB 8
#define LL 2048
#define DD 1024
#define HH 1024

// Scratch: Q proj (64MB), K proj (64MB), scores S (134MB)
__device__ float g_Q[BB * LL * HH];
__device__ float g_K[BB * LL * HH];
__device__ float g_S[(size_t)BB * LL * LL];

// ---------------------------------------------------------------------------
// Classic 128x128x16 tiled SGEMM, 256 threads, 8x8 per thread.
// TRANS_B=false: C = alpha * A(MxK,row) @ B(KxN,row) [+ bias]
// TRANS_B=true : C = alpha * A(MxK,row) @ B(NxK,row)^T [+ bias]
// blockIdx.z batches via strides.
// ---------------------------------------------------------------------------
template <bool TRANS_B, bool ADD_BIAS>
__global__ __launch_bounds__(256) void gemm128(
    const float* __restrict__ A, const float* __restrict__ B,
    const float* __restrict__ bias, float* __restrict__ C,
    int M, int N, int K, float alpha,
    size_t sA, size_t sB, size_t sC)
{
    constexpr int BM = 128, BN = 128, BK = 16;
    A += (size_t)blockIdx.z * sA;
    B += (size_t)blockIdx.z * sB;
    C += (size_t)blockIdx.z * sC;

    __shared__ float As[BK][BM];
    __shared__ float Bs[BK][BN];

    const int t  = threadIdx.x;
    const int tx = t & 15;       // 0..15 -> N direction
    const int ty = t >> 4;       // 0..15 -> M direction
    const int rowBase = blockIdx.y * BM;
    const int colBase = blockIdx.x * BN;

    float acc[8][8];
#pragma unroll
    for (int i = 0; i < 8; i++)
#pragma unroll
        for (int j = 0; j < 8; j++) acc[i][j] = 0.0f;

    for (int kt = 0; kt < K; kt += BK) {
        // Load A tile (128 rows x 16 k), 2 float4 per thread, store transposed.
#pragma unroll
        for (int v = 0; v < 2; v++) {
            int vid = t + v * 256;            // 0..511
            int r   = vid >> 2;               // row within tile (0..127)
            int c4  = (vid & 3) * 4;          // k offset (0,4,8,12)
            float4 f = *(const float4*)(A + (size_t)(rowBase + r) * K + kt + c4);
            As[c4 + 0][r] = f.x;
            As[c4 + 1][r] = f.y;
            As[c4 + 2][r] = f.z;
            As[c4 + 3][r] = f.w;
        }
        if (TRANS_B) {
            // B is (N x K) row-major; Bs[k][n] = B[n][k]
#pragma unroll
            for (int v = 0; v < 2; v++) {
                int vid = t + v * 256;
                int r   = vid >> 2;           // n within tile
                int c4  = (vid & 3) * 4;      // k offset
                float4 f = *(const float4*)(B + (size_t)(colBase + r) * K + kt + c4);
                Bs[c4 + 0][r] = f.x;
                Bs[c4 + 1][r] = f.y;
                Bs[c4 + 2][r] = f.z;
                Bs[c4 + 3][r] = f.w;
            }
        } else {
            // B is (K x N) row-major; direct vectorized copy
#pragma unroll
            for (int v = 0; v < 2; v++) {
                int vid = t + v * 256;
                int r   = vid >> 5;           // k within tile (0..15)
                int c4  = (vid & 31) * 4;     // n offset
                *(float4*)(&Bs[r][c4]) =
                    *(const float4*)(B + (size_t)(kt + r) * N + colBase + c4);
            }
        }
        __syncthreads();

#pragma unroll
        for (int k = 0; k < BK; k++) {
            float ra[8], rb[8];
#pragma unroll
            for (int i = 0; i < 4; i++) {
                float4 fa = *(const float4*)(&As[k][ty * 8 + i * 4]);
                ra[i * 4 + 0] = fa.x; ra[i * 4 + 1] = fa.y;
                ra[i * 4 + 2] = fa.z; ra[i * 4 + 3] = fa.w;
                // (two float4 per side)
                if (i >= 2) break;
            }
            {
                float4 fa0 = *(const float4*)(&As[k][ty * 8 + 0]);
                float4 fa1 = *(const float4*)(&As[k][ty * 8 + 4]);
                ra[0] = fa0.x; ra[1] = fa0.y; ra[2] = fa0.z; ra[3] = fa0.w;
                ra[4] = fa1.x; ra[5] = fa1.y; ra[6] = fa1.z; ra[7] = fa1.w;
                float4 fb0 = *(const float4*)(&Bs[k][tx * 8 + 0]);
                float4 fb1 = *(const float4*)(&Bs[k][tx * 8 + 4]);
                rb[0] = fb0.x; rb[1] = fb0.y; rb[2] = fb0.z; rb[3] = fb0.w;
                rb[4] = fb1.x; rb[5] = fb1.y; rb[6] = fb1.z; rb[7] = fb1.w;
            }
#pragma unroll
            for (int i = 0; i < 8; i++)
#pragma unroll
                for (int j = 0; j < 8; j++)
                    acc[i][j] += ra[i] * rb[j];
        }
        __syncthreads();
    }

    // Epilogue
#pragma unroll
    for (int i = 0; i < 8; i++) {
        int r = rowBase + ty * 8 + i;
        float* crow = C + (size_t)r * N + colBase + tx * 8;
        float4 o0, o1;
        float v[8];
#pragma unroll
        for (int j = 0; j < 8; j++) {
            float x = acc[i][j] * alpha;
            if (ADD_BIAS) x += bias[colBase + tx * 8 + j];
            v[j] = x;
        }
        o0.x = v[0]; o0.y = v[1]; o0.z = v[2]; o0.w = v[3];
        o1.x = v[4]; o1.y = v[5]; o1.z = v[6]; o1.w = v[7];
        *(float4*)(crow + 0) = o0;
        *(float4*)(crow + 4) = o1;
    }
}

// ---------------------------------------------------------------------------
// Fused additive-mask + softmax over rows of S (length LL=2048).
// add_mask[q,k] = m_q * m_k with m = (mask > 0.5) ? 0 : -1e9  (fp32, faithful)
// One block (256 threads) per row; row stays in registers (8 floats/thread).
// ---------------------------------------------------------------------------
__global__ __launch_bounds__(256) void softmax_mask(
    float* __restrict__ S, const float* __restrict__ mask)
{
    const int row = blockIdx.x;            // b*LL + q
    const int b   = row >> 11;
    const int q   = row & (LL - 1);
    const float* mrow = mask + (size_t)b * LL;
    const float mq = (mrow[q] > 0.5f) ? 0.0f : -1.0e9f;
    float* srow = S + (size_t)row * LL;

    const int t = threadIdx.x;
    float vals[8];
    float lmax = -INFINITY;

#pragma unroll
    for (int v = 0; v < 2; v++) {
        int idx = v * 1024 + t * 4;        // coalesced float4
        float4 f  = *(const float4*)(srow + idx);
        float4 mk = *(const float4*)(mrow + idx);
        float a;
        a = ((mk.x > 0.5f) ? 0.0f : -1.0e9f) * mq; vals[v * 4 + 0] = f.x + a;
        a = ((mk.y > 0.5f) ? 0.0f : -1.0e9f) * mq; vals[v * 4 + 1] = f.y + a;
        a = ((mk.z > 0.5f) ? 0.0f : -1.0e9f) * mq; vals[v * 4 + 2] = f.z + a;
        a = ((mk.w > 0.5f) ? 0.0f : -1.0e9f) * mq; vals[v * 4 + 3] = f.w + a;
#pragma unroll
        for (int j = 0; j < 4; j++) lmax = fmaxf(lmax, vals[v * 4 + j]);
    }

    __shared__ float red[256];
    red[t] = lmax;
    __syncthreads();
#pragma unroll
    for (int s = 128; s > 0; s >>= 1) {
        if (t < s) red[t] = fmaxf(red[t], red[t + s]);
        __syncthreads();
    }
    const float rmax = red[0];
    __syncthreads();

    float lsum = 0.0f;
#pragma unroll
    for (int i = 0; i < 8; i++) {
        vals[i] = expf(vals[i] - rmax);
        lsum += vals[i];
    }
    red[t] = lsum;
    __syncthreads();
#pragma unroll
    for (int s = 128; s > 0; s >>= 1) {
        if (t < s) red[t] += red[t + s];
        __syncthreads();
    }
    const float inv = 1.0f / red[0];

#pragma unroll
    for (int v = 0; v < 2; v++) {
        int idx = v * 1024 + t * 4;
        float4 o;
        o.x = vals[v * 4 + 0] * inv;
        o.y = vals[v * 4 + 1] * inv;
        o.z = vals[v * 4 + 2] * inv;
        o.w = vals[v * 4 + 3] * inv;
        *(float4*)(srow + idx) = o;
    }
}

// ---------------------------------------------------------------------------
extern "C" void kernel_launch(void* const* d_in, const int* in_sizes, int n_in,
                              void* d_out, int out_size)
{
    const float* in_q  = (const float*)d_in[0];
    const float* in_k  = (const float*)d_in[1];
    const float* kmask = (const float*)d_in[2];
    const float* Wq    = (const float*)d_in[3];
    const float* bq    = (const float*)d_in[4];
    const float* Wk    = (const float*)d_in[5];
    const float* bk    = (const float*)d_in[6];
    float* out = (float*)d_out;

    float *Qp, *Kp, *Sp;
    cudaGetSymbolAddress((void**)&Qp, g_Q);
    cudaGetSymbolAddress((void**)&Kp, g_K);
    cudaGetSymbolAddress((void**)&Sp, g_S);

    // 1) Projections: Q = in_q @ Wq + bq ; K = in_k @ Wk + bk
    {
        dim3 grid(HH / 128, (BB * LL) / 128, 1);
        gemm128<false, true><<<grid, 256>>>(in_q, Wq, bq, Qp,
                                            BB * LL, HH, DD, 1.0f, 0, 0, 0);
        gemm128<false, true><<<grid, 256>>>(in_k, Wk, bk, Kp,
                                            BB * LL, HH, DD, 1.0f, 0, 0, 0);
    }

    // 2) Scores: S[b] = (Q[b] @ K[b]^T) / sqrt(H)   (NT gemm, batched)
    {
        dim3 grid(LL / 128, LL / 128, BB);
        gemm128<true, false><<<grid, 256>>>(Qp, Kp, nullptr, Sp,
                                            LL, LL, HH, 0.03125f,
                                            (size_t)LL * HH, (size_t)LL * HH,
                                            (size_t)LL * LL);
    }

    // 3) Masked softmax over rows of S
    softmax_mask<<<BB * LL, 256>>>(Sp, kmask);

    // 4) Output: out[b] = P[b] @ input_k[b]   (NN gemm, batched)
    {
        dim3 grid(DD / 128, LL / 128, BB);
        gemm128<false, false><<<grid, 256>>>(Sp, in_k, nullptr, out,
                                             LL, DD, LL, 1.0f,
                                             (size_t)LL * LL, (size_t)LL * DD,
                                             (size_t)LL * DD);
    }
}

// round 5
// speedup vs baseline: 2.2554x; 2.2554x over previous
#include <cuda_runtime.h>
#include <cuda_bf16.h>
#include <math.h>
#include <stdint.h>

#define BB 8
#define LL 2048
#define DD 1024
#define HH 1024

// ---------------------------------------------------------------------------
// Scratch (bf16 split pairs + fp32 scores)
// ---------------------------------------------------------------------------
__device__ __nv_bfloat16 g_iq_h[BB * LL * DD], g_iq_l[BB * LL * DD];   // 32MB x2
__device__ __nv_bfloat16 g_ik_h[BB * LL * DD], g_ik_l[BB * LL * DD];   // 32MB x2
__device__ __nv_bfloat16 g_Wqt_h[HH * DD], g_Wqt_l[HH * DD];           // 2MB x2
__device__ __nv_bfloat16 g_Wkt_h[HH * DD], g_Wkt_l[HH * DD];
__device__ __nv_bfloat16 g_Q_h[BB * LL * HH], g_Q_l[BB * LL * HH];     // 32MB x2
__device__ __nv_bfloat16 g_K_h[BB * LL * HH], g_K_l[BB * LL * HH];
__device__ __nv_bfloat16 g_Vt_h[BB * DD * LL], g_Vt_l[BB * DD * LL];   // 32MB x2
__device__ __nv_bfloat16 g_P_h[(size_t)BB * LL * LL], g_P_l[(size_t)BB * LL * LL]; // 64MB x2
__device__ float g_S[(size_t)BB * LL * LL];                            // 128MB

// ---------------------------------------------------------------------------
__device__ __forceinline__ uint32_t smem_u32(const void* p) {
    uint32_t a;
    asm("{ .reg .u64 t; cvta.to.shared.u64 t, %1; cvt.u32.u64 %0, t; }" : "=r"(a) : "l"(p));
    return a;
}

#define CP_ASYNC16(dst, src) \
    asm volatile("cp.async.cg.shared.global [%0], [%1], 16;" :: "r"(dst), "l"(src))
#define CP_COMMIT() asm volatile("cp.async.commit_group;" ::: "memory")
#define CP_WAIT(n)  asm volatile("cp.async.wait_group %0;" :: "n"(n) : "memory")

#define LDSM4(R, addr) \
    asm volatile("ldmatrix.sync.aligned.m8n8.x4.shared.b16 {%0,%1,%2,%3}, [%4];" \
        : "=r"((R)[0]), "=r"((R)[1]), "=r"((R)[2]), "=r"((R)[3]) : "r"(addr))

#define MMA16816(D, A, B0, B1) \
    asm volatile("mma.sync.aligned.m16n8k16.row.col.f32.bf16.bf16.f32 " \
        "{%0,%1,%2,%3},{%4,%5,%6,%7},{%8,%9},{%0,%1,%2,%3};" \
        : "+f"((D)[0]), "+f"((D)[1]), "+f"((D)[2]), "+f"((D)[3]) \
        : "r"((A)[0]), "r"((A)[1]), "r"((A)[2]), "r"((A)[3]), "r"(B0), "r"(B1))

__device__ __forceinline__ void split_val(float x, __nv_bfloat16& h, __nv_bfloat16& l) {
    h = __float2bfloat16(x);
    l = __float2bfloat16(x - __bfloat162float(h));
}

// ---------------------------------------------------------------------------
// bf16x3 NT GEMM: C[m,n] = alpha * sum_k A[m,k]*B[n,k] (+bias[n])
// A,B given as hi/lo bf16 pairs, [M,K] / [N,K] row-major.
// 128x128 tile, BK=32, cp.async double buffer, 8 warps (4m x 2n), mma.sync.
// Smem row stride 80B (32 bf16 = 64B data + 16B pad) -> conflict-free ldmatrix.
// ---------------------------------------------------------------------------
#define TILE_A   10240          // 128 rows * 80B
#define STAGE_SZ 40960          // Ah, Al, Bh, Bl tiles
template <bool ADD_BIAS, bool SPLIT_OUT>
__global__ __launch_bounds__(256) void gemm_bf16x3(
    const __nv_bfloat16* __restrict__ Ah, const __nv_bfloat16* __restrict__ Al,
    const __nv_bfloat16* __restrict__ Bh, const __nv_bfloat16* __restrict__ Bl,
    const float* __restrict__ bias,
    float* __restrict__ Cf, __nv_bfloat16* __restrict__ Ch, __nv_bfloat16* __restrict__ Cl,
    int M, int N, int K, float alpha, size_t sA, size_t sB, size_t sC)
{
    extern __shared__ char smem[];
    const uint32_t sbase = smem_u32(smem);

    Ah += (size_t)blockIdx.z * sA;  Al += (size_t)blockIdx.z * sA;
    Bh += (size_t)blockIdx.z * sB;  Bl += (size_t)blockIdx.z * sB;
    if (SPLIT_OUT) { Ch += (size_t)blockIdx.z * sC; Cl += (size_t)blockIdx.z * sC; }
    else           { Cf += (size_t)blockIdx.z * sC; }

    const int t    = threadIdx.x;
    const int lane = t & 31;
    const int wid  = t >> 5;
    const int wm   = wid & 3;          // 4 warps along M (32 rows each)
    const int wn   = wid >> 2;         // 2 warps along N (64 cols each)
    const int rowBase = blockIdx.y * 128;
    const int colBase = blockIdx.x * 128;

    const int nIter = K >> 5;

    auto produce = [&](int kt, int stage) {
        const uint32_t s0 = sbase + stage * STAGE_SZ;
        const int k0 = kt << 5;
#pragma unroll
        for (int i = 0; i < 2; i++) {
            int c   = t + i * 256;          // 0..511
            int r   = c >> 2;               // row 0..127
            int seg = c & 3;                // 16B segment (8 bf16)
            uint32_t sof = (uint32_t)(r * 80 + seg * 16);
            size_t  gof  = (size_t)(rowBase + r) * K + k0 + seg * 8;
            size_t  gob  = (size_t)(colBase + r) * K + k0 + seg * 8;
            CP_ASYNC16(s0 + sof,                Ah + gof);
            CP_ASYNC16(s0 + TILE_A + sof,       Al + gof);
            CP_ASYNC16(s0 + 2 * TILE_A + sof,   Bh + gob);
            CP_ASYNC16(s0 + 3 * TILE_A + sof,   Bl + gob);
        }
        CP_COMMIT();
    };

    float acc[2][8][4];
#pragma unroll
    for (int i = 0; i < 2; i++)
#pragma unroll
        for (int j = 0; j < 8; j++)
#pragma unroll
            for (int v = 0; v < 4; v++) acc[i][j][v] = 0.0f;

    produce(0, 0);

    for (int kt = 0; kt < nIter; kt++) {
        const int stage = kt & 1;
        if (kt + 1 < nIter) { produce(kt + 1, stage ^ 1); CP_WAIT(1); }
        else                { CP_WAIT(0); }
        __syncthreads();

        const uint32_t sA0 = sbase + stage * STAGE_SZ;
        const uint32_t sB0 = sA0 + 2 * TILE_A;

#pragma unroll
        for (int ks = 0; ks < 2; ks++) {
            const int kk = ks * 16;
            uint32_t ah[2][4], al[2][4], bh[8][2], bl[8][2];
#pragma unroll
            for (int mt = 0; mt < 2; mt++) {
                int m0 = wm * 32 + mt * 16;
                uint32_t r = m0 + (lane & 7) + ((lane >> 3) & 1) * 8;
                uint32_t c = kk + ((lane >> 4) & 1) * 8;
                uint32_t ad = sA0 + r * 80 + c * 2;
                LDSM4(ah[mt], ad);
                LDSM4(al[mt], ad + TILE_A);
            }
#pragma unroll
            for (int np = 0; np < 4; np++) {
                int n0 = wn * 64 + np * 16;
                uint32_t r = n0 + (lane & 7) + ((lane >> 4) & 1) * 8;
                uint32_t c = kk + ((lane >> 3) & 1) * 8;
                uint32_t ad = sB0 + r * 80 + c * 2;
                LDSM4(&bh[2 * np][0], ad);
                LDSM4(&bl[2 * np][0], ad + TILE_A);
            }
#pragma unroll
            for (int mt = 0; mt < 2; mt++)
#pragma unroll
                for (int nt = 0; nt < 8; nt++) {
                    MMA16816(acc[mt][nt], ah[mt], bh[nt][0], bh[nt][1]);
                    MMA16816(acc[mt][nt], ah[mt], bl[nt][0], bl[nt][1]);
                    MMA16816(acc[mt][nt], al[mt], bh[nt][0], bh[nt][1]);
                }
        }
        __syncthreads();
    }

    // Epilogue
#pragma unroll
    for (int mt = 0; mt < 2; mt++) {
#pragma unroll
        for (int nt = 0; nt < 8; nt++) {
            int row = rowBase + wm * 32 + mt * 16 + (lane >> 2);
            int col = colBase + wn * 64 + nt * 8 + 2 * (lane & 3);
            float v0 = acc[mt][nt][0] * alpha;
            float v1 = acc[mt][nt][1] * alpha;
            float v2 = acc[mt][nt][2] * alpha;
            float v3 = acc[mt][nt][3] * alpha;
            if (ADD_BIAS) {
                float b0 = bias[col], b1 = bias[col + 1];
                v0 += b0; v1 += b1; v2 += b0; v3 += b1;
            }
            if (SPLIT_OUT) {
                __nv_bfloat162 h01, l01, h23, l23;
                split_val(v0, h01.x, l01.x); split_val(v1, h01.y, l01.y);
                split_val(v2, h23.x, l23.x); split_val(v3, h23.y, l23.y);
                *(__nv_bfloat162*)(Ch + (size_t)row * N + col)       = h01;
                *(__nv_bfloat162*)(Cl + (size_t)row * N + col)       = l01;
                *(__nv_bfloat162*)(Ch + (size_t)(row + 8) * N + col) = h23;
                *(__nv_bfloat162*)(Cl + (size_t)(row + 8) * N + col) = l23;
            } else {
                *(float2*)(Cf + (size_t)row * N + col)       = make_float2(v0, v1);
                *(float2*)(Cf + (size_t)(row + 8) * N + col) = make_float2(v2, v3);
            }
        }
    }
}

// ---------------------------------------------------------------------------
// Elementwise fp32 -> (hi, lo) bf16 split. 4 elements / thread.
// ---------------------------------------------------------------------------
__global__ __launch_bounds__(256) void split_f32(
    const float* __restrict__ in, __nv_bfloat16* __restrict__ h,
    __nv_bfloat16* __restrict__ l)
{
    size_t i = ((size_t)blockIdx.x * 256 + threadIdx.x) * 4;
    float4 v = *(const float4*)(in + i);
    __nv_bfloat162 h01, l01, h23, l23;
    split_val(v.x, h01.x, l01.x); split_val(v.y, h01.y, l01.y);
    split_val(v.z, h23.x, l23.x); split_val(v.w, h23.y, l23.y);
    *(__nv_bfloat162*)(h + i)     = h01;
    *(__nv_bfloat162*)(l + i)     = l01;
    *(__nv_bfloat162*)(h + i + 2) = h23;
    *(__nv_bfloat162*)(l + i + 2) = l23;
}

// ---------------------------------------------------------------------------
// Transpose + split: out_{h,l}[c][r] = split(in[r][c]); batched over z.
// ---------------------------------------------------------------------------
__global__ __launch_bounds__(256) void transpose_split(
    const float* __restrict__ in, __nv_bfloat16* __restrict__ oh,
    __nv_bfloat16* __restrict__ ol, int R, int C)
{
    __shared__ float tile[32][33];
    in += (size_t)blockIdx.z * R * C;
    oh += (size_t)blockIdx.z * R * C;
    ol += (size_t)blockIdx.z * R * C;
    const int r0 = blockIdx.y * 32, c0 = blockIdx.x * 32;
    const int tx = threadIdx.x, ty = threadIdx.y;
#pragma unroll
    for (int i = ty; i < 32; i += 8)
        tile[i][tx] = in[(size_t)(r0 + i) * C + c0 + tx];
    __syncthreads();
#pragma unroll
    for (int i = ty; i < 32; i += 8) {
        float x = tile[tx][i];
        __nv_bfloat16 h, l;
        split_val(x, h, l);
        size_t o = (size_t)(c0 + i) * R + r0 + tx;
        oh[o] = h;
        ol[o] = l;
    }
}

// ---------------------------------------------------------------------------
// Fused mask + softmax; reads fp32 S, writes split bf16 P.
// ---------------------------------------------------------------------------
__global__ __launch_bounds__(256) void softmax_mask(
    const float* __restrict__ S, const float* __restrict__ mask,
    __nv_bfloat16* __restrict__ Ph, __nv_bfloat16* __restrict__ Pl)
{
    const int row = blockIdx.x;
    const int b   = row >> 11;
    const int q   = row & (LL - 1);
    const float* mrow = mask + (size_t)b * LL;
    const float mq = (mrow[q] > 0.5f) ? 0.0f : -1.0e9f;
    const float* srow = S + (size_t)row * LL;

    const int t = threadIdx.x;
    float vals[8];
    float lmax = -INFINITY;

#pragma unroll
    for (int v = 0; v < 2; v++) {
        int idx = v * 1024 + t * 4;
        float4 f  = *(const float4*)(srow + idx);
        float4 mk = *(const float4*)(mrow + idx);
        float a;
        a = ((mk.x > 0.5f) ? 0.0f : -1.0e9f) * mq; vals[v * 4 + 0] = f.x + a;
        a = ((mk.y > 0.5f) ? 0.0f : -1.0e9f) * mq; vals[v * 4 + 1] = f.y + a;
        a = ((mk.z > 0.5f) ? 0.0f : -1.0e9f) * mq; vals[v * 4 + 2] = f.z + a;
        a = ((mk.w > 0.5f) ? 0.0f : -1.0e9f) * mq; vals[v * 4 + 3] = f.w + a;
#pragma unroll
        for (int j = 0; j < 4; j++) lmax = fmaxf(lmax, vals[v * 4 + j]);
    }

    __shared__ float red[256];
    red[t] = lmax;
    __syncthreads();
#pragma unroll
    for (int s = 128; s > 0; s >>= 1) {
        if (t < s) red[t] = fmaxf(red[t], red[t + s]);
        __syncthreads();
    }
    const float rmax = red[0];
    __syncthreads();

    float lsum = 0.0f;
#pragma unroll
    for (int i = 0; i < 8; i++) {
        vals[i] = expf(vals[i] - rmax);
        lsum += vals[i];
    }
    red[t] = lsum;
    __syncthreads();
#pragma unroll
    for (int s = 128; s > 0; s >>= 1) {
        if (t < s) red[t] += red[t + s];
        __syncthreads();
    }
    const float inv = 1.0f / red[0];

#pragma unroll
    for (int v = 0; v < 2; v++) {
        int idx = v * 1024 + t * 4;
        float p0 = vals[v * 4 + 0] * inv, p1 = vals[v * 4 + 1] * inv;
        float p2 = vals[v * 4 + 2] * inv, p3 = vals[v * 4 + 3] * inv;
        __nv_bfloat162 h01, l01, h23, l23;
        split_val(p0, h01.x, l01.x); split_val(p1, h01.y, l01.y);
        split_val(p2, h23.x, l23.x); split_val(p3, h23.y, l23.y);
        size_t o = (size_t)row * LL + idx;
        *(__nv_bfloat162*)(Ph + o)     = h01;
        *(__nv_bfloat162*)(Pl + o)     = l01;
        *(__nv_bfloat162*)(Ph + o + 2) = h23;
        *(__nv_bfloat162*)(Pl + o + 2) = l23;
    }
}

// ---------------------------------------------------------------------------
extern "C" void kernel_launch(void* const* d_in, const int* in_sizes, int n_in,
                              void* d_out, int out_size)
{
    const float* in_q  = (const float*)d_in[0];
    const float* in_k  = (const float*)d_in[1];
    const float* kmask = (const float*)d_in[2];
    const float* Wq    = (const float*)d_in[3];
    const float* bq    = (const float*)d_in[4];
    const float* Wk    = (const float*)d_in[5];
    const float* bk    = (const float*)d_in[6];
    float* out = (float*)d_out;

    __nv_bfloat16 *iqh, *iql, *ikh, *ikl, *wqh, *wql, *wkh, *wkl;
    __nv_bfloat16 *Qh, *Ql, *Kh, *Kl, *Vh, *Vl, *Ph, *Pl;
    float* Sp;
    cudaGetSymbolAddress((void**)&iqh, g_iq_h);  cudaGetSymbolAddress((void**)&iql, g_iq_l);
    cudaGetSymbolAddress((void**)&ikh, g_ik_h);  cudaGetSymbolAddress((void**)&ikl, g_ik_l);
    cudaGetSymbolAddress((void**)&wqh, g_Wqt_h); cudaGetSymbolAddress((void**)&wql, g_Wqt_l);
    cudaGetSymbolAddress((void**)&wkh, g_Wkt_h); cudaGetSymbolAddress((void**)&wkl, g_Wkt_l);
    cudaGetSymbolAddress((void**)&Qh,  g_Q_h);   cudaGetSymbolAddress((void**)&Ql,  g_Q_l);
    cudaGetSymbolAddress((void**)&Kh,  g_K_h);   cudaGetSymbolAddress((void**)&Kl,  g_K_l);
    cudaGetSymbolAddress((void**)&Vh,  g_Vt_h);  cudaGetSymbolAddress((void**)&Vl,  g_Vt_l);
    cudaGetSymbolAddress((void**)&Ph,  g_P_h);   cudaGetSymbolAddress((void**)&Pl,  g_P_l);
    cudaGetSymbolAddress((void**)&Sp,  g_S);

    const int SMEM_BYTES = 2 * STAGE_SZ;   // 81920
    cudaFuncSetAttribute(gemm_bf16x3<true, true>,
                         cudaFuncAttributeMaxDynamicSharedMemorySize, SMEM_BYTES);
    cudaFuncSetAttribute(gemm_bf16x3<false, false>,
                         cudaFuncAttributeMaxDynamicSharedMemorySize, SMEM_BYTES);

    // 0) Splits + transposed splits
    split_f32<<<BB * LL * DD / 1024, 256>>>(in_q, iqh, iql);
    split_f32<<<BB * LL * DD / 1024, 256>>>(in_k, ikh, ikl);
    {
        dim3 blk(32, 8);
        transpose_split<<<dim3(HH / 32, DD / 32, 1), blk>>>(Wq, wqh, wql, DD, HH);
        transpose_split<<<dim3(HH / 32, DD / 32, 1), blk>>>(Wk, wkh, wkl, DD, HH);
        transpose_split<<<dim3(DD / 32, LL / 32, BB), blk>>>(in_k, Vh, Vl, LL, DD);
    }

    // 1) Projections (NT, split output): Q = in_q @ Wq + bq ; K = in_k @ Wk + bk
    {
        dim3 grid(HH / 128, (BB * LL) / 128, 1);
        gemm_bf16x3<true, true><<<grid, 256, SMEM_BYTES>>>(
            iqh, iql, wqh, wql, bq, nullptr, Qh, Ql,
            BB * LL, HH, DD, 1.0f, 0, 0, 0);
        gemm_bf16x3<true, true><<<grid, 256, SMEM_BYTES>>>(
            ikh, ikl, wkh, wkl, bk, nullptr, Kh, Kl,
            BB * LL, HH, DD, 1.0f, 0, 0, 0);
    }

    // 2) Scores: S[b] = (Q[b] @ K[b]^T) / 32
    {
        dim3 grid(LL / 128, LL / 128, BB);
        gemm_bf16x3<false, false><<<grid, 256, SMEM_BYTES>>>(
            Qh, Ql, Kh, Kl, nullptr, Sp, nullptr, nullptr,
            LL, LL, HH, 0.03125f,
            (size_t)LL * HH, (size_t)LL * HH, (size_t)LL * LL);
    }

    // 3) Masked softmax -> split P
    softmax_mask<<<BB * LL, 256>>>(Sp, kmask, Ph, Pl);

    // 4) Output: out[b] = P[b] @ in_k[b]  (NT with Vt)
    {
        dim3 grid(DD / 128, LL / 128, BB);
        gemm_bf16x3<false, false><<<grid, 256, SMEM_BYTES>>>(
            Ph, Pl, Vh, Vl, nullptr, out, nullptr, nullptr,
            LL, DD, LL, 1.0f,
            (size_t)LL * LL, (size_t)DD * LL, (size_t)LL * DD);
    }
}

// round 6
// speedup vs baseline: 2.6697x; 1.1837x over previous
#include <cuda_runtime.h>
#include <cuda_bf16.h>
#include <math.h>
#include <stdint.h>

#define BB 8
#define LL 2048
#define DD 1024
#define HH 1024

// ---------------------------------------------------------------------------
// Scratch (bf16 split pairs + fp32 scores)
// ---------------------------------------------------------------------------
__device__ __nv_bfloat16 g_iq_h[BB * LL * DD], g_iq_l[BB * LL * DD];
__device__ __nv_bfloat16 g_ik_h[BB * LL * DD], g_ik_l[BB * LL * DD];
__device__ __nv_bfloat16 g_Wqt_h[HH * DD], g_Wqt_l[HH * DD];
__device__ __nv_bfloat16 g_Wkt_h[HH * DD], g_Wkt_l[HH * DD];
__device__ __nv_bfloat16 g_Q_h[BB * LL * HH], g_Q_l[BB * LL * HH];
__device__ __nv_bfloat16 g_K_h[BB * LL * HH], g_K_l[BB * LL * HH];
__device__ __nv_bfloat16 g_Vt_h[BB * DD * LL], g_Vt_l[BB * DD * LL];
__device__ __nv_bfloat16 g_P_h[(size_t)BB * LL * LL], g_P_l[(size_t)BB * LL * LL];
__device__ float g_S[(size_t)BB * LL * LL];

// ---------------------------------------------------------------------------
__device__ __forceinline__ uint32_t smem_u32(const void* p) {
    uint32_t a;
    asm("{ .reg .u64 t; cvta.to.shared.u64 t, %1; cvt.u32.u64 %0, t; }" : "=r"(a) : "l"(p));
    return a;
}

#define CP_ASYNC16(dst, src) \
    asm volatile("cp.async.cg.shared.global [%0], [%1], 16;" :: "r"(dst), "l"(src))
#define CP_COMMIT() asm volatile("cp.async.commit_group;" ::: "memory")
#define CP_WAIT(n)  asm volatile("cp.async.wait_group %0;" :: "n"(n) : "memory")

#define LDSM4(R, addr) \
    asm volatile("ldmatrix.sync.aligned.m8n8.x4.shared.b16 {%0,%1,%2,%3}, [%4];" \
        : "=r"((R)[0]), "=r"((R)[1]), "=r"((R)[2]), "=r"((R)[3]) : "r"(addr))

#define MMA16816(D, A, B0, B1) \
    asm volatile("mma.sync.aligned.m16n8k16.row.col.f32.bf16.bf16.f32 " \
        "{%0,%1,%2,%3},{%4,%5,%6,%7},{%8,%9},{%0,%1,%2,%3};" \
        : "+f"((D)[0]), "+f"((D)[1]), "+f"((D)[2]), "+f"((D)[3]) \
        : "r"((A)[0]), "r"((A)[1]), "r"((A)[2]), "r"((A)[3]), "r"(B0), "r"(B1))

__device__ __forceinline__ void split_val(float x, __nv_bfloat16& h, __nv_bfloat16& l) {
    h = __float2bfloat16(x);
    l = __float2bfloat16(x - __bfloat162float(h));
}

// ---------------------------------------------------------------------------
// bf16x3 NT GEMM: C[m,n] = alpha * sum_k A[m,k]*B[n,k] (+bias[n])
// 128x128 tile, BK=32, cp.async double buffer, 8 warps (4m x 2n), mma.sync.
// Smem row stride 80B; MMAs issued in 3 passes (hh, hl, lh) so each
// accumulator's reuse distance is 16 MMAs (no RAW stalls on HMMA).
// ---------------------------------------------------------------------------
#define TILE_A   10240          // 128 rows * 80B
#define STAGE_SZ 40960          // Ah, Al, Bh, Bl tiles
template <bool ADD_BIAS, bool SPLIT_OUT>
__global__ __launch_bounds__(256, 2) void gemm_bf16x3(
    const __nv_bfloat16* __restrict__ Ah, const __nv_bfloat16* __restrict__ Al,
    const __nv_bfloat16* __restrict__ Bh, const __nv_bfloat16* __restrict__ Bl,
    const float* __restrict__ bias,
    float* __restrict__ Cf, __nv_bfloat16* __restrict__ Ch, __nv_bfloat16* __restrict__ Cl,
    int M, int N, int K, float alpha, size_t sA, size_t sB, size_t sC)
{
    extern __shared__ char smem[];
    const uint32_t sbase = smem_u32(smem);

    Ah += (size_t)blockIdx.z * sA;  Al += (size_t)blockIdx.z * sA;
    Bh += (size_t)blockIdx.z * sB;  Bl += (size_t)blockIdx.z * sB;
    if (SPLIT_OUT) { Ch += (size_t)blockIdx.z * sC; Cl += (size_t)blockIdx.z * sC; }
    else           { Cf += (size_t)blockIdx.z * sC; }

    const int t    = threadIdx.x;
    const int lane = t & 31;
    const int wid  = t >> 5;
    const int wm   = wid & 3;          // 4 warps along M (32 rows each)
    const int wn   = wid >> 2;         // 2 warps along N (64 cols each)
    const int rowBase = blockIdx.y * 128;
    const int colBase = blockIdx.x * 128;

    const int nIter = K >> 5;

    // Precomputed ldmatrix base offsets (relative to stage base), per ks via +32B.
    //   A frag rows: wm*32 + mt*16 + (lane&7) + ((lane>>3)&1)*8 ; col ((lane>>4)&1)*8
    //   B frag rows: wn*64 + np*16 + (lane&7) + ((lane>>4)&1)*8 ; col ((lane>>3)&1)*8
    uint32_t aoff[2], boff[4];
#pragma unroll
    for (int mt = 0; mt < 2; mt++) {
        uint32_t r = wm * 32 + mt * 16 + (lane & 7) + ((lane >> 3) & 1) * 8;
        uint32_t c = ((lane >> 4) & 1) * 8;
        aoff[mt] = r * 80 + c * 2;
    }
#pragma unroll
    for (int np = 0; np < 4; np++) {
        uint32_t r = wn * 64 + np * 16 + (lane & 7) + ((lane >> 4) & 1) * 8;
        uint32_t c = ((lane >> 3) & 1) * 8;
        boff[np] = 2 * TILE_A + r * 80 + c * 2;
    }

    // Producer offsets
    const int pr  = t >> 2;            // row 0..63 (+64 with second load)
    const int pseg = (t & 3) * 16;     // 16B segment in row
    const uint32_t psof = (uint32_t)(pr * 80 + pseg);
    const int pk = (t & 3) * 8;

    auto produce = [&](int kt, int stage) {
        const uint32_t s0 = sbase + stage * STAGE_SZ;
        const int k0 = kt << 5;
#pragma unroll
        for (int i = 0; i < 2; i++) {
            int r = pr + i * 64;
            uint32_t sof = psof + (uint32_t)i * (64 * 80);
            size_t gof = (size_t)(rowBase + r) * K + k0 + pk;
            size_t gob = (size_t)(colBase + r) * K + k0 + pk;
            CP_ASYNC16(s0 + sof,              Ah + gof);
            CP_ASYNC16(s0 + TILE_A + sof,     Al + gof);
            CP_ASYNC16(s0 + 2 * TILE_A + sof, Bh + gob);
            CP_ASYNC16(s0 + 3 * TILE_A + sof, Bl + gob);
        }
        CP_COMMIT();
    };

    float acc[2][8][4];
#pragma unroll
    for (int i = 0; i < 2; i++)
#pragma unroll
        for (int j = 0; j < 8; j++)
#pragma unroll
            for (int v = 0; v < 4; v++) acc[i][j][v] = 0.0f;

    produce(0, 0);

    for (int kt = 0; kt < nIter; kt++) {
        const int stage = kt & 1;
        if (kt + 1 < nIter) { produce(kt + 1, stage ^ 1); CP_WAIT(1); }
        else                { CP_WAIT(0); }
        __syncthreads();

        const uint32_t s0 = sbase + stage * STAGE_SZ;

#pragma unroll
        for (int ks = 0; ks < 2; ks++) {
            const uint32_t kof = ks * 32;   // 16 bf16 = 32B
            uint32_t ah[2][4], al[2][4], bh[8][2], bl[8][2];
#pragma unroll
            for (int mt = 0; mt < 2; mt++) {
                uint32_t ad = s0 + aoff[mt] + kof;
                LDSM4(ah[mt], ad);
                LDSM4(al[mt], ad + TILE_A);
            }
#pragma unroll
            for (int np = 0; np < 4; np++) {
                uint32_t ad = s0 + boff[np] + kof;
                LDSM4(&bh[2 * np][0], ad);
                LDSM4(&bl[2 * np][0], ad + TILE_A);
            }
            // Pass 1: hi*hi  (acc reuse distance = 16 MMAs)
#pragma unroll
            for (int mt = 0; mt < 2; mt++)
#pragma unroll
                for (int nt = 0; nt < 8; nt++)
                    MMA16816(acc[mt][nt], ah[mt], bh[nt][0], bh[nt][1]);
            // Pass 2: hi*lo
#pragma unroll
            for (int mt = 0; mt < 2; mt++)
#pragma unroll
                for (int nt = 0; nt < 8; nt++)
                    MMA16816(acc[mt][nt], ah[mt], bl[nt][0], bl[nt][1]);
            // Pass 3: lo*hi
#pragma unroll
            for (int mt = 0; mt < 2; mt++)
#pragma unroll
                for (int nt = 0; nt < 8; nt++)
                    MMA16816(acc[mt][nt], al[mt], bh[nt][0], bh[nt][1]);
        }
        __syncthreads();
    }

    // Epilogue
#pragma unroll
    for (int mt = 0; mt < 2; mt++) {
#pragma unroll
        for (int nt = 0; nt < 8; nt++) {
            int row = rowBase + wm * 32 + mt * 16 + (lane >> 2);
            int col = colBase + wn * 64 + nt * 8 + 2 * (lane & 3);
            float v0 = acc[mt][nt][0] * alpha;
            float v1 = acc[mt][nt][1] * alpha;
            float v2 = acc[mt][nt][2] * alpha;
            float v3 = acc[mt][nt][3] * alpha;
            if (ADD_BIAS) {
                float b0 = bias[col], b1 = bias[col + 1];
                v0 += b0; v1 += b1; v2 += b0; v3 += b1;
            }
            if (SPLIT_OUT) {
                __nv_bfloat162 h01, l01, h23, l23;
                split_val(v0, h01.x, l01.x); split_val(v1, h01.y, l01.y);
                split_val(v2, h23.x, l23.x); split_val(v3, h23.y, l23.y);
                *(__nv_bfloat162*)(Ch + (size_t)row * N + col)       = h01;
                *(__nv_bfloat162*)(Cl + (size_t)row * N + col)       = l01;
                *(__nv_bfloat162*)(Ch + (size_t)(row + 8) * N + col) = h23;
                *(__nv_bfloat162*)(Cl + (size_t)(row + 8) * N + col) = l23;
            } else {
                *(float2*)(Cf + (size_t)row * N + col)       = make_float2(v0, v1);
                *(float2*)(Cf + (size_t)(row + 8) * N + col) = make_float2(v2, v3);
            }
        }
    }
}

// ---------------------------------------------------------------------------
// Elementwise fp32 -> (hi, lo) bf16 split. 4 elements / thread.
// ---------------------------------------------------------------------------
__global__ __launch_bounds__(256) void split_f32(
    const float* __restrict__ in, __nv_bfloat16* __restrict__ h,
    __nv_bfloat16* __restrict__ l)
{
    size_t i = ((size_t)blockIdx.x * 256 + threadIdx.x) * 4;
    float4 v = *(const float4*)(in + i);
    __nv_bfloat162 h01, l01, h23, l23;
    split_val(v.x, h01.x, l01.x); split_val(v.y, h01.y, l01.y);
    split_val(v.z, h23.x, l23.x); split_val(v.w, h23.y, l23.y);
    *(__nv_bfloat162*)(h + i)     = h01;
    *(__nv_bfloat162*)(l + i)     = l01;
    *(__nv_bfloat162*)(h + i + 2) = h23;
    *(__nv_bfloat162*)(l + i + 2) = l23;
}

// ---------------------------------------------------------------------------
// Transpose + split: out_{h,l}[c][r] = split(in[r][c]); batched over z.
// ---------------------------------------------------------------------------
__global__ __launch_bounds__(256) void transpose_split(
    const float* __restrict__ in, __nv_bfloat16* __restrict__ oh,
    __nv_bfloat16* __restrict__ ol, int R, int C)
{
    __shared__ float tile[32][33];
    in += (size_t)blockIdx.z * R * C;
    oh += (size_t)blockIdx.z * R * C;
    ol += (size_t)blockIdx.z * R * C;
    const int r0 = blockIdx.y * 32, c0 = blockIdx.x * 32;
    const int tx = threadIdx.x, ty = threadIdx.y;
#pragma unroll
    for (int i = ty; i < 32; i += 8)
        tile[i][tx] = in[(size_t)(r0 + i) * C + c0 + tx];
    __syncthreads();
#pragma unroll
    for (int i = ty; i < 32; i += 8) {
        float x = tile[tx][i];
        __nv_bfloat16 h, l;
        split_val(x, h, l);
        size_t o = (size_t)(c0 + i) * R + r0 + tx;
        oh[o] = h;
        ol[o] = l;
    }
}

// ---------------------------------------------------------------------------
// Fused mask + softmax; reads fp32 S, writes split bf16 P.
// ---------------------------------------------------------------------------
__global__ __launch_bounds__(256) void softmax_mask(
    const float* __restrict__ S, const float* __restrict__ mask,
    __nv_bfloat16* __restrict__ Ph, __nv_bfloat16* __restrict__ Pl)
{
    const int row = blockIdx.x;
    const int b   = row >> 11;
    const int q   = row & (LL - 1);
    const float* mrow = mask + (size_t)b * LL;
    const float mq = (mrow[q] > 0.5f) ? 0.0f : -1.0e9f;
    const float* srow = S + (size_t)row * LL;

    const int t = threadIdx.x;
    float vals[8];
    float lmax = -INFINITY;

#pragma unroll
    for (int v = 0; v < 2; v++) {
        int idx = v * 1024 + t * 4;
        float4 f  = *(const float4*)(srow + idx);
        float4 mk = *(const float4*)(mrow + idx);
        float a;
        a = ((mk.x > 0.5f) ? 0.0f : -1.0e9f) * mq; vals[v * 4 + 0] = f.x + a;
        a = ((mk.y > 0.5f) ? 0.0f : -1.0e9f) * mq; vals[v * 4 + 1] = f.y + a;
        a = ((mk.z > 0.5f) ? 0.0f : -1.0e9f) * mq; vals[v * 4 + 2] = f.z + a;
        a = ((mk.w > 0.5f) ? 0.0f : -1.0e9f) * mq; vals[v * 4 + 3] = f.w + a;
#pragma unroll
        for (int j = 0; j < 4; j++) lmax = fmaxf(lmax, vals[v * 4 + j]);
    }

    __shared__ float red[256];
    red[t] = lmax;
    __syncthreads();
#pragma unroll
    for (int s = 128; s > 0; s >>= 1) {
        if (t < s) red[t] = fmaxf(red[t], red[t + s]);
        __syncthreads();
    }
    const float rmax = red[0];
    __syncthreads();

    float lsum = 0.0f;
#pragma unroll
    for (int i = 0; i < 8; i++) {
        vals[i] = expf(vals[i] - rmax);
        lsum += vals[i];
    }
    red[t] = lsum;
    __syncthreads();
#pragma unroll
    for (int s = 128; s > 0; s >>= 1) {
        if (t < s) red[t] += red[t + s];
        __syncthreads();
    }
    const float inv = 1.0f / red[0];

#pragma unroll
    for (int v = 0; v < 2; v++) {
        int idx = v * 1024 + t * 4;
        float p0 = vals[v * 4 + 0] * inv, p1 = vals[v * 4 + 1] * inv;
        float p2 = vals[v * 4 + 2] * inv, p3 = vals[v * 4 + 3] * inv;
        __nv_bfloat162 h01, l01, h23, l23;
        split_val(p0, h01.x, l01.x); split_val(p1, h01.y, l01.y);
        split_val(p2, h23.x, l23.x); split_val(p3, h23.y, l23.y);
        size_t o = (size_t)row * LL + idx;
        *(__nv_bfloat162*)(Ph + o)     = h01;
        *(__nv_bfloat162*)(Pl + o)     = l01;
        *(__nv_bfloat162*)(Ph + o + 2) = h23;
        *(__nv_bfloat162*)(Pl + o + 2) = l23;
    }
}

// ---------------------------------------------------------------------------
extern "C" void kernel_launch(void* const* d_in, const int* in_sizes, int n_in,
                              void* d_out, int out_size)
{
    const float* in_q  = (const float*)d_in[0];
    const float* in_k  = (const float*)d_in[1];
    const float* kmask = (const float*)d_in[2];
    const float* Wq    = (const float*)d_in[3];
    const float* bq    = (const float*)d_in[4];
    const float* Wk    = (const float*)d_in[5];
    const float* bk    = (const float*)d_in[6];
    float* out = (float*)d_out;

    __nv_bfloat16 *iqh, *iql, *ikh, *ikl, *wqh, *wql, *wkh, *wkl;
    __nv_bfloat16 *Qh, *Ql, *Kh, *Kl, *Vh, *Vl, *Ph, *Pl;
    float* Sp;
    cudaGetSymbolAddress((void**)&iqh, g_iq_h);  cudaGetSymbolAddress((void**)&iql, g_iq_l);
    cudaGetSymbolAddress((void**)&ikh, g_ik_h);  cudaGetSymbolAddress((void**)&ikl, g_ik_l);
    cudaGetSymbolAddress((void**)&wqh, g_Wqt_h); cudaGetSymbolAddress((void**)&wql, g_Wqt_l);
    cudaGetSymbolAddress((void**)&wkh, g_Wkt_h); cudaGetSymbolAddress((void**)&wkl, g_Wkt_l);
    cudaGetSymbolAddress((void**)&Qh,  g_Q_h);   cudaGetSymbolAddress((void**)&Ql,  g_Q_l);
    cudaGetSymbolAddress((void**)&Kh,  g_K_h);   cudaGetSymbolAddress((void**)&Kl,  g_K_l);
    cudaGetSymbolAddress((void**)&Vh,  g_Vt_h);  cudaGetSymbolAddress((void**)&Vl,  g_Vt_l);
    cudaGetSymbolAddress((void**)&Ph,  g_P_h);   cudaGetSymbolAddress((void**)&Pl,  g_P_l);
    cudaGetSymbolAddress((void**)&Sp,  g_S);

    const int SMEM_BYTES = 2 * STAGE_SZ;   // 81920
    cudaFuncSetAttribute(gemm_bf16x3<true, true>,
                         cudaFuncAttributeMaxDynamicSharedMemorySize, SMEM_BYTES);
    cudaFuncSetAttribute(gemm_bf16x3<false, false>,
                         cudaFuncAttributeMaxDynamicSharedMemorySize, SMEM_BYTES);

    // 0) Splits + transposed splits
    split_f32<<<BB * LL * DD / 1024, 256>>>(in_q, iqh, iql);
    split_f32<<<BB * LL * DD / 1024, 256>>>(in_k, ikh, ikl);
    {
        dim3 blk(32, 8);
        transpose_split<<<dim3(HH / 32, DD / 32, 1), blk>>>(Wq, wqh, wql, DD, HH);
        transpose_split<<<dim3(HH / 32, DD / 32, 1), blk>>>(Wk, wkh, wkl, DD, HH);
        transpose_split<<<dim3(DD / 32, LL / 32, BB), blk>>>(in_k, Vh, Vl, LL, DD);
    }

    // 1) Projections (NT, split output)
    {
        dim3 grid(HH / 128, (BB * LL) / 128, 1);
        gemm_bf16x3<true, true><<<grid, 256, SMEM_BYTES>>>(
            iqh, iql, wqh, wql, bq, nullptr, Qh, Ql,
            BB * LL, HH, DD, 1.0f, 0, 0, 0);
        gemm_bf16x3<true, true><<<grid, 256, SMEM_BYTES>>>(
            ikh, ikl, wkh, wkl, bk, nullptr, Kh, Kl,
            BB * LL, HH, DD, 1.0f, 0, 0, 0);
    }

    // 2) Scores: S[b] = (Q[b] @ K[b]^T) / 32
    {
        dim3 grid(LL / 128, LL / 128, BB);
        gemm_bf16x3<false, false><<<grid, 256, SMEM_BYTES>>>(
            Qh, Ql, Kh, Kl, nullptr, Sp, nullptr, nullptr,
            LL, LL, HH, 0.03125f,
            (size_t)LL * HH, (size_t)LL * HH, (size_t)LL * LL);
    }

    // 3) Masked softmax -> split P
    softmax_mask<<<BB * LL, 256>>>(Sp, kmask, Ph, Pl);

    // 4) Output: out[b] = P[b] @ in_k[b]  (NT with Vt)
    {
        dim3 grid(DD / 128, LL / 128, BB);
        gemm_bf16x3<false, false><<<grid, 256, SMEM_BYTES>>>(
            Ph, Pl, Vh, Vl, nullptr, out, nullptr, nullptr,
            LL, DD, LL, 1.0f,
            (size_t)LL * LL, (size_t)DD * LL, (size_t)LL * DD);
    }
}